// round 1
// baseline (speedup 1.0000x reference)
#include <cuda_runtime.h>
#include <cstdint>

// TopicLayer: out[t,b,c,l] for c<128  = sum_d emb[b,l,d]*topic_w[t,c,d] + topic_b[t,c]
//             out[t,b,128+f,l]       = sum_d emb[b,l,d]*shared_w[f,d] + shared_b[f]
// Shapes: B=16, L=1024, D=512, T=32, FT=128, FS=128.
// Treated as GEMM C[4224,16384] = W[4224,512] * X^T[512,16384], plus bias,
// with last 128 rows broadcast across the 32 topics on output.

#define BM 128
#define BN 128
#define BK 16

__global__ __launch_bounds__(256, 2)
void topic_gemm_kernel(const float* __restrict__ emb,
                       const float* __restrict__ topic_w,
                       const float* __restrict__ topic_b,
                       const float* __restrict__ shared_w,
                       const float* __restrict__ shared_b,
                       float* __restrict__ out)
{
    __shared__ float As[2][BK][BM];
    __shared__ float Bs[2][BK][BN];

    const int tileN = blockIdx.x;   // 0..127 -> column tile (within one batch row-block)
    const int tileM = blockIdx.y;   // 0..32  -> row tile; 32 == shared filters
    const int tid   = threadIdx.x;

    const bool is_shared = (tileM == 32);
    const float* Wp = is_shared ? shared_w : (topic_w + (size_t)tileM * (128 * 512));
    const float* bp = is_shared ? shared_b : (topic_b + tileM * 128);

    const int bIdx = tileN >> 3;          // batch index (1024/128 = 8 tiles per batch)
    const int l0   = (tileN & 7) * BN;    // l offset within the sequence
    const float* Bp = emb + ((size_t)(bIdx * 1024 + l0)) * 512;

    // ---- loader indices: 256 threads, each loads 2 float4 of A and 2 of B per k-tile
    const int lr = tid & 127;   // row within tile (A: filter row, B: token row)
    const int kh = (tid >> 7) * 8;  // k sub-offset: 0 or 8

    // ---- compute indices: 16x16 threads, 8x8 micro-tile as 2x2 blocks of 4x4
    const int tx = tid & 15;
    const int ty = tid >> 4;

    float acc[2][2][4][4];
#pragma unroll
    for (int i = 0; i < 2; i++)
#pragma unroll
        for (int j = 0; j < 2; j++)
#pragma unroll
            for (int a = 0; a < 4; a++)
#pragma unroll
                for (int b = 0; b < 4; b++) acc[i][j][a][b] = 0.f;

    // ---- preload k-tile 0 into buffer 0
    {
        const float* ag = Wp + (size_t)lr * 512 + kh;
        float4 a0 = *(const float4*)(ag);
        float4 a1 = *(const float4*)(ag + 4);
        const float* bg = Bp + (size_t)lr * 512 + kh;
        float4 b0 = *(const float4*)(bg);
        float4 b1 = *(const float4*)(bg + 4);
        As[0][kh + 0][lr] = a0.x; As[0][kh + 1][lr] = a0.y;
        As[0][kh + 2][lr] = a0.z; As[0][kh + 3][lr] = a0.w;
        As[0][kh + 4][lr] = a1.x; As[0][kh + 5][lr] = a1.y;
        As[0][kh + 6][lr] = a1.z; As[0][kh + 7][lr] = a1.w;
        Bs[0][kh + 0][lr] = b0.x; Bs[0][kh + 1][lr] = b0.y;
        Bs[0][kh + 2][lr] = b0.z; Bs[0][kh + 3][lr] = b0.w;
        Bs[0][kh + 4][lr] = b1.x; Bs[0][kh + 5][lr] = b1.y;
        Bs[0][kh + 6][lr] = b1.z; Bs[0][kh + 7][lr] = b1.w;
    }
    __syncthreads();

    const int NKT = 512 / BK;  // 32 k-tiles
    for (int kt = 0; kt < NKT; ++kt) {
        const int cur = kt & 1;

        // prefetch next k-tile from global into registers
        float4 pa0, pa1, pb0, pb1;
        if (kt < NKT - 1) {
            const float* ag = Wp + (size_t)lr * 512 + (kt + 1) * BK + kh;
            pa0 = *(const float4*)(ag);
            pa1 = *(const float4*)(ag + 4);
            const float* bg = Bp + (size_t)lr * 512 + (kt + 1) * BK + kh;
            pb0 = *(const float4*)(bg);
            pb1 = *(const float4*)(bg + 4);
        }

        // compute on current buffer
#pragma unroll
        for (int kk = 0; kk < BK; ++kk) {
            float4 a0v = *(const float4*)(&As[cur][kk][ty * 4]);
            float4 a1v = *(const float4*)(&As[cur][kk][ty * 4 + 64]);
            float4 b0v = *(const float4*)(&Bs[cur][kk][tx * 4]);
            float4 b1v = *(const float4*)(&Bs[cur][kk][tx * 4 + 64]);
            float af[2][4] = {{a0v.x, a0v.y, a0v.z, a0v.w},
                              {a1v.x, a1v.y, a1v.z, a1v.w}};
            float bf[2][4] = {{b0v.x, b0v.y, b0v.z, b0v.w},
                              {b1v.x, b1v.y, b1v.z, b1v.w}};
#pragma unroll
            for (int i = 0; i < 2; i++)
#pragma unroll
                for (int j = 0; j < 2; j++)
#pragma unroll
                    for (int a = 0; a < 4; a++)
#pragma unroll
                        for (int b = 0; b < 4; b++)
                            acc[i][j][a][b] += af[i][a] * bf[j][b];
        }

        // store prefetched tile into the other buffer
        if (kt < NKT - 1) {
            const int nxt = cur ^ 1;
            As[nxt][kh + 0][lr] = pa0.x; As[nxt][kh + 1][lr] = pa0.y;
            As[nxt][kh + 2][lr] = pa0.z; As[nxt][kh + 3][lr] = pa0.w;
            As[nxt][kh + 4][lr] = pa1.x; As[nxt][kh + 5][lr] = pa1.y;
            As[nxt][kh + 6][lr] = pa1.z; As[nxt][kh + 7][lr] = pa1.w;
            Bs[nxt][kh + 0][lr] = pb0.x; Bs[nxt][kh + 1][lr] = pb0.y;
            Bs[nxt][kh + 2][lr] = pb0.z; Bs[nxt][kh + 3][lr] = pb0.w;
            Bs[nxt][kh + 4][lr] = pb1.x; Bs[nxt][kh + 5][lr] = pb1.y;
            Bs[nxt][kh + 6][lr] = pb1.z; Bs[nxt][kh + 7][lr] = pb1.w;
            __syncthreads();
        }
    }

    // ---- epilogue: bias + store
    // out layout: [T=32, B=16, C=256, L=1024]; base col for this tile:
    //   column j = bIdx*1024 + l0 + n, contiguous in n per tile.
    if (!is_shared) {
        const int t = tileM;
        const size_t base = ((size_t)(t * 16 + bIdx) * 256) * 1024 + l0;
#pragma unroll
        for (int i = 0; i < 2; i++) {
#pragma unroll
            for (int a = 0; a < 4; a++) {
                const int r = i * 64 + ty * 4 + a;  // channel 0..127
                const float bias = bp[r];
#pragma unroll
                for (int j = 0; j < 2; j++) {
                    float4 v;
                    v.x = acc[i][j][a][0] + bias;
                    v.y = acc[i][j][a][1] + bias;
                    v.z = acc[i][j][a][2] + bias;
                    v.w = acc[i][j][a][3] + bias;
                    const int n = j * 64 + tx * 4;
                    *(float4*)&out[base + (size_t)r * 1024 + n] = v;
                }
            }
        }
    } else {
        // shared-filter tile: channels 128..255, broadcast to all 32 topics
#pragma unroll
        for (int i = 0; i < 2; i++) {
#pragma unroll
            for (int a = 0; a < 4; a++) {
                const int r = i * 64 + ty * 4 + a;  // 0..127 -> channel 128+r
                const float bias = bp[r];
                float4 v0, v1;
                v0.x = acc[i][0][a][0] + bias; v0.y = acc[i][0][a][1] + bias;
                v0.z = acc[i][0][a][2] + bias; v0.w = acc[i][0][a][3] + bias;
                v1.x = acc[i][1][a][0] + bias; v1.y = acc[i][1][a][1] + bias;
                v1.z = acc[i][1][a][2] + bias; v1.w = acc[i][1][a][3] + bias;
                for (int t = 0; t < 32; ++t) {
                    const size_t base =
                        ((size_t)(t * 16 + bIdx) * 256 + 128 + r) * 1024 + l0;
                    *(float4*)&out[base + tx * 4]      = v0;
                    *(float4*)&out[base + 64 + tx * 4] = v1;
                }
            }
        }
    }
}

extern "C" void kernel_launch(void* const* d_in, const int* in_sizes, int n_in,
                              void* d_out, int out_size) {
    const float* emb      = (const float*)d_in[0];  // [16,1024,512]
    const float* topic_w  = (const float*)d_in[1];  // [32,128,512]
    const float* topic_b  = (const float*)d_in[2];  // [32,128]
    const float* shared_w = (const float*)d_in[3];  // [128,512]
    const float* shared_b = (const float*)d_in[4];  // [128]
    float* out = (float*)d_out;                     // [32,16,256,1024]

    dim3 grid(128, 33);  // 128 col tiles x (32 topic row-tiles + 1 shared row-tile)
    topic_gemm_kernel<<<grid, 256>>>(emb, topic_w, topic_b, shared_w, shared_b, out);
}

// round 5
// speedup vs baseline: 2.5225x; 2.5225x over previous
#include <cuda_runtime.h>
#include <cuda_fp16.h>
#include <cstdint>

// ============================================================================
// TopicLayer as GEMM C[4224,16384] = W[4224,512] * X^T via mma.sync m16n8k16
// fp16 3-term split (AhBh + AhBl + AlBh), fp32 accumulate.
// out[t,b,c,l]: c<128 -> topic filter rows t*128+c; c>=128 -> shared rows
// 4096+(c-128), broadcast over t (shared row-tile replicated 4x, 8 copies ea).
// Both A and B are K-major in smem -> BOTH use non-trans ldmatrix (row.col TN).
// ============================================================================

#define DDIM 512
#define M_ROWS 4224
#define NKT 16               // 512 / 32
#define KT 32                // k elems per stage

#define STAGE_BYTES 49152    // Ah 8K + Al 8K + Bh 16K + Bl 16K
#define A_H_OFF 0
#define A_L_OFF 8192
#define B_H_OFF 16384
#define B_L_OFF 32768
#define SMEM_TOTAL (2 * STAGE_BYTES)

// fp16 split scratch (static device memory — allocation-free)
__device__ __half g_w_hi[M_ROWS * DDIM];
__device__ __half g_w_lo[M_ROWS * DDIM];
__device__ __half g_e_hi[16 * 1024 * DDIM];
__device__ __half g_e_lo[16 * 1024 * DDIM];

// ---------------------------------------------------------------------------
__device__ __forceinline__ uint32_t smem_u32(const void* p) {
    uint32_t a;
    asm("{ .reg .u64 t; cvta.to.shared.u64 t, %1; cvt.u32.u64 %0, t; }"
        : "=r"(a) : "l"(p));
    return a;
}
__device__ __forceinline__ void cpa16(uint32_t dst, const void* src) {
    asm volatile("cp.async.cg.shared.global [%0], [%1], 16;"
                 :: "r"(dst), "l"(src));
}
__device__ __forceinline__ void cp_commit() {
    asm volatile("cp.async.commit_group;" ::: "memory");
}
__device__ __forceinline__ void cp_wait0() {
    asm volatile("cp.async.wait_group 0;" ::: "memory");
}
__device__ __forceinline__ void cp_wait1() {
    asm volatile("cp.async.wait_group 1;" ::: "memory");
}
__device__ __forceinline__ void ldsm4(uint32_t* r, uint32_t addr) {
    asm volatile("ldmatrix.sync.aligned.m8n8.x4.shared.b16 {%0,%1,%2,%3}, [%4];"
                 : "=r"(r[0]), "=r"(r[1]), "=r"(r[2]), "=r"(r[3]) : "r"(addr));
}
__device__ __forceinline__ void mma16816(float* d, const uint32_t* a,
                                         const uint32_t* b) {
    asm volatile(
        "mma.sync.aligned.m16n8k16.row.col.f32.f16.f16.f32 "
        "{%0,%1,%2,%3}, {%4,%5,%6,%7}, {%8,%9}, {%0,%1,%2,%3};"
        : "+f"(d[0]), "+f"(d[1]), "+f"(d[2]), "+f"(d[3])
        : "r"(a[0]), "r"(a[1]), "r"(a[2]), "r"(a[3]), "r"(b[0]), "r"(b[1]));
}

// smem offset for (row, 16B-granule g), 64B rows, XOR swizzle on granules
__device__ __forceinline__ uint32_t swoff(int row, int g) {
    return (uint32_t)(row * 64 + ((g ^ ((row >> 1) & 3)) << 4));
}

// ---------------------------------------------------------------------------
// fp32 -> fp16 hi/lo split prologue kernels
// ---------------------------------------------------------------------------
__global__ void convert_emb_kernel(const float* __restrict__ emb) {
    int i = blockIdx.x * blockDim.x + threadIdx.x;   // 2097152 float4
    float4 v = ((const float4*)emb)[i];
    __half h0 = __float2half(v.x), h1 = __float2half(v.y);
    __half h2 = __float2half(v.z), h3 = __float2half(v.w);
    __half l0 = __float2half(v.x - __half2float(h0));
    __half l1 = __float2half(v.y - __half2float(h1));
    __half l2 = __float2half(v.z - __half2float(h2));
    __half l3 = __float2half(v.w - __half2float(h3));
    __half2* ph = (__half2*)&g_e_hi[(size_t)i * 4];
    ph[0] = __halves2half2(h0, h1);
    ph[1] = __halves2half2(h2, h3);
    __half2* pl = (__half2*)&g_e_lo[(size_t)i * 4];
    pl[0] = __halves2half2(l0, l1);
    pl[1] = __halves2half2(l2, l3);
}

__global__ void convert_w_kernel(const float* __restrict__ topic_w,
                                 const float* __restrict__ shared_w) {
    int i = blockIdx.x * blockDim.x + threadIdx.x;   // 540672 float4
    const int topic_vec = (4096 * 512) / 4;
    float4 v = (i < topic_vec) ? ((const float4*)topic_w)[i]
                               : ((const float4*)shared_w)[i - topic_vec];
    __half h0 = __float2half(v.x), h1 = __float2half(v.y);
    __half h2 = __float2half(v.z), h3 = __float2half(v.w);
    __half l0 = __float2half(v.x - __half2float(h0));
    __half l1 = __float2half(v.y - __half2float(h1));
    __half l2 = __float2half(v.z - __half2float(h2));
    __half l3 = __float2half(v.w - __half2float(h3));
    __half2* ph = (__half2*)&g_w_hi[(size_t)i * 4];
    ph[0] = __halves2half2(h0, h1);
    ph[1] = __halves2half2(h2, h3);
    __half2* pl = (__half2*)&g_w_lo[(size_t)i * 4];
    pl[0] = __halves2half2(l0, l1);
    pl[1] = __halves2half2(l2, l3);
}

// ---------------------------------------------------------------------------
// stage loader: A (128x32 h+l) + B (256x32 h+l), 16B cp.async chunks
// ---------------------------------------------------------------------------
__device__ __forceinline__ void issue_stage(
    uint32_t sbuf, int tid, int kt,
    const __half* __restrict__ Wh, const __half* __restrict__ Wl,
    const __half* __restrict__ Eh, const __half* __restrict__ El)
{
    const int koff = kt * KT;
#pragma unroll
    for (int i = 0; i < 2; i++) {          // A: 512 chunks per matrix
        int c = tid + i * 256;
        int row = c >> 2, g = c & 3;
        uint32_t d = swoff(row, g);
        const __half* s = Wh + (size_t)row * DDIM + koff + g * 8;
        cpa16(sbuf + A_H_OFF + d, s);
        s = Wl + (size_t)row * DDIM + koff + g * 8;
        cpa16(sbuf + A_L_OFF + d, s);
    }
#pragma unroll
    for (int i = 0; i < 4; i++) {          // B: 1024 chunks per matrix
        int c = tid + i * 256;
        int row = c >> 2, g = c & 3;
        uint32_t d = swoff(row, g);
        cpa16(sbuf + B_H_OFF + d, Eh + (size_t)row * DDIM + koff + g * 8);
        cpa16(sbuf + B_L_OFF + d, El + (size_t)row * DDIM + koff + g * 8);
    }
}

// ---------------------------------------------------------------------------
// Main GEMM: grid (64, 36). x: bIdx*4 + l-tile (N=256). y<32: topic row tile
// (M=128 = one topic). y in 32..35: shared rows, each replica writes 8 topics.
// 8 warps, each 64x64 via m16n8k16.
// ---------------------------------------------------------------------------
__global__ __launch_bounds__(256, 1)
void topic_mma_kernel(const float* __restrict__ topic_b,
                      const float* __restrict__ shared_b,
                      float* __restrict__ out)
{
    extern __shared__ char smem[];
    const uint32_t sb = smem_u32(smem);
    const int tid = threadIdx.x;
    const int wid = tid >> 5, lane = tid & 31;
    const int wm = wid & 1, wn = wid >> 1;   // warp grid 2(M) x 4(N)

    const int tileN = blockIdx.x;
    const int tileM = blockIdx.y;
    const bool is_sh = (tileM >= 32);
    const int m0 = is_sh ? 4096 : tileM * 128;
    const int bIdx = tileN >> 2;
    const int l0 = (tileN & 3) * 256;

    const __half* Wh = g_w_hi + (size_t)m0 * DDIM;
    const __half* Wl = g_w_lo + (size_t)m0 * DDIM;
    const __half* Eh = g_e_hi + (size_t)(bIdx * 1024 + l0) * DDIM;
    const __half* El = g_e_lo + (size_t)(bIdx * 1024 + l0) * DDIM;

    // ldmatrix lane-address components (non-trans for BOTH operands: K-major)
    const int a_row = wm * 64 + (lane & 15);
    const int a_gl = lane >> 4;
    const uint32_t a_sw = ((lane & 15) >> 1) & 3;
    const int b_row = wn * 64 + (lane & 7) + ((lane >> 4) << 3);
    const int b_gl = (lane >> 3) & 1;
    const uint32_t b_sw = ((lane & 7) >> 1) & 3;

    float acc[4][8][4];
#pragma unroll
    for (int mf = 0; mf < 4; mf++)
#pragma unroll
        for (int nf = 0; nf < 8; nf++)
#pragma unroll
            for (int r = 0; r < 4; r++) acc[mf][nf][r] = 0.f;

    issue_stage(sb, tid, 0, Wh, Wl, Eh, El);
    cp_commit();

    for (int kt = 0; kt < NKT; ++kt) {
        if (kt < NKT - 1) {
            issue_stage(sb + ((kt + 1) & 1) * STAGE_BYTES, tid, kt + 1,
                        Wh, Wl, Eh, El);
            cp_commit();
            cp_wait1();
        } else {
            cp_wait0();
        }
        __syncthreads();

        const uint32_t st = sb + (kt & 1) * STAGE_BYTES;
#pragma unroll
        for (int kk = 0; kk < 2; kk++) {
            uint32_t ah[4][4], al[4][4], bb[4][4];
#pragma unroll
            for (int mf = 0; mf < 4; mf++) {
                uint32_t off = (uint32_t)((a_row + mf * 16) * 64) +
                               (((kk * 2 + a_gl) ^ a_sw) << 4);
                ldsm4(ah[mf], st + A_H_OFF + off);
                ldsm4(al[mf], st + A_L_OFF + off);
            }
#pragma unroll
            for (int np = 0; np < 4; np++) {
                uint32_t off = (uint32_t)((b_row + np * 16) * 64) +
                               (((kk * 2 + b_gl) ^ b_sw) << 4);
                ldsm4(bb[np], st + B_H_OFF + off);
            }
            // Ah*Bh and Al*Bh
#pragma unroll
            for (int mf = 0; mf < 4; mf++)
#pragma unroll
                for (int np = 0; np < 4; np++) {
                    mma16816(acc[mf][np * 2],     ah[mf], &bb[np][0]);
                    mma16816(acc[mf][np * 2 + 1], ah[mf], &bb[np][2]);
                    mma16816(acc[mf][np * 2],     al[mf], &bb[np][0]);
                    mma16816(acc[mf][np * 2 + 1], al[mf], &bb[np][2]);
                }
            // reload B-lo over bb, then Ah*Bl
#pragma unroll
            for (int np = 0; np < 4; np++) {
                uint32_t off = (uint32_t)((b_row + np * 16) * 64) +
                               (((kk * 2 + b_gl) ^ b_sw) << 4);
                ldsm4(bb[np], st + B_L_OFF + off);
            }
#pragma unroll
            for (int mf = 0; mf < 4; mf++)
#pragma unroll
                for (int np = 0; np < 4; np++) {
                    mma16816(acc[mf][np * 2],     ah[mf], &bb[np][0]);
                    mma16816(acc[mf][np * 2 + 1], ah[mf], &bb[np][2]);
                }
        }
        __syncthreads();
    }

    // ---- epilogue: bias + store (32B-sector-aligned float2 stores) --------
    const float* bp = is_sh ? shared_b : (topic_b + tileM * 128);
    const int gid = lane >> 2, tig = lane & 3;
    const int cbase = l0 + wn * 64 + tig * 2;

#pragma unroll
    for (int mf = 0; mf < 4; mf++) {
        const int r0 = wm * 64 + mf * 16 + gid;
        const int r1 = r0 + 8;
        const float bias0 = bp[r0];
        const float bias1 = bp[r1];
        if (!is_sh) {
            const size_t base = ((size_t)(tileM * 16 + bIdx) * 256) * 1024;
            float* p0 = out + base + (size_t)r0 * 1024 + cbase;
            float* p1 = out + base + (size_t)r1 * 1024 + cbase;
#pragma unroll
            for (int nf = 0; nf < 8; nf++) {
                float2 v0 = make_float2(acc[mf][nf][0] + bias0,
                                        acc[mf][nf][1] + bias0);
                float2 v1 = make_float2(acc[mf][nf][2] + bias1,
                                        acc[mf][nf][3] + bias1);
                *(float2*)(p0 + nf * 8) = v0;
                *(float2*)(p1 + nf * 8) = v1;
            }
        } else {
#pragma unroll 1
            for (int tt = 0; tt < 8; tt++) {
                const int t = (tileM - 32) * 8 + tt;
                const size_t base =
                    ((size_t)(t * 16 + bIdx) * 256 + 128) * 1024;
                float* p0 = out + base + (size_t)r0 * 1024 + cbase;
                float* p1 = out + base + (size_t)r1 * 1024 + cbase;
#pragma unroll
                for (int nf = 0; nf < 8; nf++) {
                    float2 v0 = make_float2(acc[mf][nf][0] + bias0,
                                            acc[mf][nf][1] + bias0);
                    float2 v1 = make_float2(acc[mf][nf][2] + bias1,
                                            acc[mf][nf][3] + bias1);
                    *(float2*)(p0 + nf * 8) = v0;
                    *(float2*)(p1 + nf * 8) = v1;
                }
            }
        }
    }
}

// ---------------------------------------------------------------------------
extern "C" void kernel_launch(void* const* d_in, const int* in_sizes, int n_in,
                              void* d_out, int out_size) {
    const float* emb      = (const float*)d_in[0];  // [16,1024,512]
    const float* topic_w  = (const float*)d_in[1];  // [32,128,512]
    const float* topic_b  = (const float*)d_in[2];  // [32,128]
    const float* shared_w = (const float*)d_in[3];  // [128,512]
    const float* shared_b = (const float*)d_in[4];  // [128]
    float* out = (float*)d_out;                     // [32,16,256,1024]

    convert_emb_kernel<<<8192, 256>>>(emb);
    convert_w_kernel<<<2112, 256>>>(topic_w, shared_w);

    cudaFuncSetAttribute(topic_mma_kernel,
                         cudaFuncAttributeMaxDynamicSharedMemorySize,
                         SMEM_TOTAL);
    dim3 grid(64, 36);
    topic_mma_kernel<<<grid, 256, SMEM_TOTAL>>>(topic_b, shared_b, out);
}

// round 7
// speedup vs baseline: 2.9094x; 1.1534x over previous
#include <cuda_runtime.h>
#include <cuda_fp16.h>
#include <cstdint>

// ============================================================================
// TopicLayer GEMM C[4224,16384] = W[4224,512] * X^T via mma.sync m16n8k16,
// fp16 3-term split (AhBh + AhBl + AlBh), fp32 accumulate.
// This round: 128-thr CTAs (occ 2), tile 128x128, 3-stage cp.async pipeline,
// full B hi+lo fragment prefetch per kk.
// ============================================================================

#define DDIM 512
#define M_ROWS 4224
#define NKT 16               // 512 / 32
#define KT 32

#define STAGE_BYTES 32768    // Ah 8K + Al 8K + Bh 8K + Bl 8K
#define A_H_OFF 0
#define A_L_OFF 8192
#define B_H_OFF 16384
#define B_L_OFF 24576
#define NSTAGE 3
#define SMEM_TOTAL (NSTAGE * STAGE_BYTES)   // 98304

__device__ __half g_w_hi[M_ROWS * DDIM];
__device__ __half g_w_lo[M_ROWS * DDIM];
__device__ __half g_e_hi[16 * 1024 * DDIM];
__device__ __half g_e_lo[16 * 1024 * DDIM];

// ---------------------------------------------------------------------------
__device__ __forceinline__ uint32_t smem_u32(const void* p) {
    uint32_t a;
    asm("{ .reg .u64 t; cvta.to.shared.u64 t, %1; cvt.u32.u64 %0, t; }"
        : "=r"(a) : "l"(p));
    return a;
}
__device__ __forceinline__ void cpa16(uint32_t dst, const void* src) {
    asm volatile("cp.async.cg.shared.global [%0], [%1], 16;"
                 :: "r"(dst), "l"(src));
}
__device__ __forceinline__ void cp_commit() {
    asm volatile("cp.async.commit_group;" ::: "memory");
}
__device__ __forceinline__ void cp_wait0() {
    asm volatile("cp.async.wait_group 0;" ::: "memory");
}
__device__ __forceinline__ void cp_wait1() {
    asm volatile("cp.async.wait_group 1;" ::: "memory");
}
__device__ __forceinline__ void ldsm4(uint32_t* r, uint32_t addr) {
    asm volatile("ldmatrix.sync.aligned.m8n8.x4.shared.b16 {%0,%1,%2,%3}, [%4];"
                 : "=r"(r[0]), "=r"(r[1]), "=r"(r[2]), "=r"(r[3]) : "r"(addr));
}
__device__ __forceinline__ void mma16816(float* d, const uint32_t* a,
                                         const uint32_t* b) {
    asm volatile(
        "mma.sync.aligned.m16n8k16.row.col.f32.f16.f16.f32 "
        "{%0,%1,%2,%3}, {%4,%5,%6,%7}, {%8,%9}, {%0,%1,%2,%3};"
        : "+f"(d[0]), "+f"(d[1]), "+f"(d[2]), "+f"(d[3])
        : "r"(a[0]), "r"(a[1]), "r"(a[2]), "r"(a[3]), "r"(b[0]), "r"(b[1]));
}
__device__ __forceinline__ uint32_t swoff(int row, int g) {
    return (uint32_t)(row * 64 + ((g ^ ((row >> 1) & 3)) << 4));
}

// ---------------------------------------------------------------------------
__global__ void convert_emb_kernel(const float* __restrict__ emb) {
    int i = blockIdx.x * blockDim.x + threadIdx.x;   // 2097152 float4
    float4 v = ((const float4*)emb)[i];
    __half h0 = __float2half(v.x), h1 = __float2half(v.y);
    __half h2 = __float2half(v.z), h3 = __float2half(v.w);
    __half l0 = __float2half(v.x - __half2float(h0));
    __half l1 = __float2half(v.y - __half2float(h1));
    __half l2 = __float2half(v.z - __half2float(h2));
    __half l3 = __float2half(v.w - __half2float(h3));
    __half2* ph = (__half2*)&g_e_hi[(size_t)i * 4];
    ph[0] = __halves2half2(h0, h1);
    ph[1] = __halves2half2(h2, h3);
    __half2* pl = (__half2*)&g_e_lo[(size_t)i * 4];
    pl[0] = __halves2half2(l0, l1);
    pl[1] = __halves2half2(l2, l3);
}

__global__ void convert_w_kernel(const float* __restrict__ topic_w,
                                 const float* __restrict__ shared_w) {
    int i = blockIdx.x * blockDim.x + threadIdx.x;   // 540672 float4
    const int topic_vec = (4096 * 512) / 4;
    float4 v = (i < topic_vec) ? ((const float4*)topic_w)[i]
                               : ((const float4*)shared_w)[i - topic_vec];
    __half h0 = __float2half(v.x), h1 = __float2half(v.y);
    __half h2 = __float2half(v.z), h3 = __float2half(v.w);
    __half l0 = __float2half(v.x - __half2float(h0));
    __half l1 = __float2half(v.y - __half2float(h1));
    __half l2 = __float2half(v.z - __half2float(h2));
    __half l3 = __float2half(v.w - __half2float(h3));
    __half2* ph = (__half2*)&g_w_hi[(size_t)i * 4];
    ph[0] = __halves2half2(h0, h1);
    ph[1] = __halves2half2(h2, h3);
    __half2* pl = (__half2*)&g_w_lo[(size_t)i * 4];
    pl[0] = __halves2half2(l0, l1);
    pl[1] = __halves2half2(l2, l3);
}

// ---------------------------------------------------------------------------
// stage loader: A (128x32 hi+lo) + B (128x32 hi+lo); 128 threads, 16 chunks ea
// ---------------------------------------------------------------------------
__device__ __forceinline__ void issue_stage(
    uint32_t sbuf, int tid, int kt,
    const __half* __restrict__ Wh, const __half* __restrict__ Wl,
    const __half* __restrict__ Eh, const __half* __restrict__ El)
{
    const int koff = kt * KT;
#pragma unroll
    for (int i = 0; i < 4; i++) {          // 512 chunks per matrix
        int c = tid + i * 128;
        int row = c >> 2, g = c & 3;
        uint32_t d = swoff(row, g);
        const size_t goff = (size_t)row * DDIM + koff + g * 8;
        cpa16(sbuf + A_H_OFF + d, Wh + goff);
        cpa16(sbuf + A_L_OFF + d, Wl + goff);
        cpa16(sbuf + B_H_OFF + d, Eh + goff);
        cpa16(sbuf + B_L_OFF + d, El + goff);
    }
}

// ---------------------------------------------------------------------------
// Main GEMM: grid (128, 36). x: bIdx*8 + l-tile (N=128). y<32: topic tile
// (M=128). y in 32..35: shared rows, each replica writes 8 topic copies.
// 4 warps (2Mx2N), each 64x64.
// ---------------------------------------------------------------------------
__global__ __launch_bounds__(128, 2)
void topic_mma_kernel(const float* __restrict__ topic_b,
                      const float* __restrict__ shared_b,
                      float* __restrict__ out)
{
    extern __shared__ char smem[];
    const uint32_t sb = smem_u32(smem);
    const int tid = threadIdx.x;
    const int wid = tid >> 5, lane = tid & 31;
    const int wm = wid & 1, wn = wid >> 1;   // 2(M) x 2(N)

    const int tileN = blockIdx.x;            // 0..127
    const int tileM = blockIdx.y;            // 0..35
    const bool is_sh = (tileM >= 32);
    const int m0 = is_sh ? 4096 : tileM * 128;
    const int bIdx = tileN >> 3;
    const int l0 = (tileN & 7) * 128;

    const __half* Wh = g_w_hi + (size_t)m0 * DDIM;
    const __half* Wl = g_w_lo + (size_t)m0 * DDIM;
    const __half* Eh = g_e_hi + (size_t)(bIdx * 1024 + l0) * DDIM;
    const __half* El = g_e_lo + (size_t)(bIdx * 1024 + l0) * DDIM;

    // ldmatrix lane-address components (non-trans, K-major both operands)
    const int a_row = wm * 64 + (lane & 15);
    const int a_gl = lane >> 4;
    const uint32_t a_sw = ((lane & 15) >> 1) & 3;
    const int b_row = wn * 64 + (lane & 7) + ((lane >> 4) << 3);
    const int b_gl = (lane >> 3) & 1;
    const uint32_t b_sw = ((lane & 7) >> 1) & 3;

    float acc[4][8][4];
#pragma unroll
    for (int mf = 0; mf < 4; mf++)
#pragma unroll
        for (int nf = 0; nf < 8; nf++)
#pragma unroll
            for (int r = 0; r < 4; r++) acc[mf][nf][r] = 0.f;

    // 3-stage prologue: stages 0 and 1 in flight
    issue_stage(sb, tid, 0, Wh, Wl, Eh, El);
    cp_commit();
    issue_stage(sb + STAGE_BYTES, tid, 1, Wh, Wl, Eh, El);
    cp_commit();

    for (int kt = 0; kt < NKT; ++kt) {
        if (kt < NKT - 1) cp_wait1(); else cp_wait0();
        __syncthreads();

        // issue loads for kt+2 into buffer (kt+2)%3 (consumed at kt-1, safe)
        if (kt + 2 < NKT) {
            issue_stage(sb + ((kt + 2) % NSTAGE) * STAGE_BYTES, tid, kt + 2,
                        Wh, Wl, Eh, El);
            cp_commit();
        }

        const uint32_t st = sb + (kt % NSTAGE) * STAGE_BYTES;
#pragma unroll
        for (int kk = 0; kk < 2; kk++) {
            uint32_t ah[4][4], al[4][4], bh[4][4], bl[4][4];
#pragma unroll
            for (int mf = 0; mf < 4; mf++) {
                uint32_t off = (uint32_t)((a_row + mf * 16) * 64) +
                               (((kk * 2 + a_gl) ^ a_sw) << 4);
                ldsm4(ah[mf], st + A_H_OFF + off);
                ldsm4(al[mf], st + A_L_OFF + off);
            }
#pragma unroll
            for (int np = 0; np < 4; np++) {
                uint32_t off = (uint32_t)((b_row + np * 16) * 64) +
                               (((kk * 2 + b_gl) ^ b_sw) << 4);
                ldsm4(bh[np], st + B_H_OFF + off);
                ldsm4(bl[np], st + B_L_OFF + off);
            }
#pragma unroll
            for (int mf = 0; mf < 4; mf++)
#pragma unroll
                for (int np = 0; np < 4; np++) {
                    mma16816(acc[mf][np * 2],     ah[mf], &bh[np][0]);
                    mma16816(acc[mf][np * 2 + 1], ah[mf], &bh[np][2]);
                    mma16816(acc[mf][np * 2],     al[mf], &bh[np][0]);
                    mma16816(acc[mf][np * 2 + 1], al[mf], &bh[np][2]);
                    mma16816(acc[mf][np * 2],     ah[mf], &bl[np][0]);
                    mma16816(acc[mf][np * 2 + 1], ah[mf], &bl[np][2]);
                }
        }
    }

    // ---- epilogue: bias + float2 stores ----------------------------------
    const float* bp = is_sh ? shared_b : (topic_b + tileM * 128);
    const int gid = lane >> 2, tig = lane & 3;
    const int cbase = l0 + wn * 64 + tig * 2;

#pragma unroll
    for (int mf = 0; mf < 4; mf++) {
        const int r0 = wm * 64 + mf * 16 + gid;
        const int r1 = r0 + 8;
        const float bias0 = bp[r0];
        const float bias1 = bp[r1];
        if (!is_sh) {
            const size_t base = ((size_t)(tileM * 16 + bIdx) * 256) * 1024;
            float* p0 = out + base + (size_t)r0 * 1024 + cbase;
            float* p1 = out + base + (size_t)r1 * 1024 + cbase;
#pragma unroll
            for (int nf = 0; nf < 8; nf++) {
                float2 v0 = make_float2(acc[mf][nf][0] + bias0,
                                        acc[mf][nf][1] + bias0);
                float2 v1 = make_float2(acc[mf][nf][2] + bias1,
                                        acc[mf][nf][3] + bias1);
                *(float2*)(p0 + nf * 8) = v0;
                *(float2*)(p1 + nf * 8) = v1;
            }
        } else {
#pragma unroll 1
            for (int tt = 0; tt < 8; tt++) {
                const int t = (tileM - 32) * 8 + tt;
                const size_t base =
                    ((size_t)(t * 16 + bIdx) * 256 + 128) * 1024;
                float* p0 = out + base + (size_t)r0 * 1024 + cbase;
                float* p1 = out + base + (size_t)r1 * 1024 + cbase;
#pragma unroll
                for (int nf = 0; nf < 8; nf++) {
                    float2 v0 = make_float2(acc[mf][nf][0] + bias0,
                                            acc[mf][nf][1] + bias0);
                    float2 v1 = make_float2(acc[mf][nf][2] + bias1,
                                            acc[mf][nf][3] + bias1);
                    *(float2*)(p0 + nf * 8) = v0;
                    *(float2*)(p1 + nf * 8) = v1;
                }
            }
        }
    }
}

// ---------------------------------------------------------------------------
extern "C" void kernel_launch(void* const* d_in, const int* in_sizes, int n_in,
                              void* d_out, int out_size) {
    const float* emb      = (const float*)d_in[0];  // [16,1024,512]
    const float* topic_w  = (const float*)d_in[1];  // [32,128,512]
    const float* topic_b  = (const float*)d_in[2];  // [32,128]
    const float* shared_w = (const float*)d_in[3];  // [128,512]
    const float* shared_b = (const float*)d_in[4];  // [128]
    float* out = (float*)d_out;                     // [32,16,256,1024]

    convert_emb_kernel<<<8192, 256>>>(emb);
    convert_w_kernel<<<2112, 256>>>(topic_w, shared_w);

    cudaFuncSetAttribute(topic_mma_kernel,
                         cudaFuncAttributeMaxDynamicSharedMemorySize,
                         SMEM_TOTAL);
    dim3 grid(128, 36);
    topic_mma_kernel<<<grid, 128, SMEM_TOTAL>>>(topic_b, shared_b, out);
}

// round 8
// speedup vs baseline: 4.0504x; 1.3922x over previous
#include <cuda_runtime.h>
#include <cuda_fp16.h>
#include <cstdint>

// ============================================================================
// TopicLayer GEMM C[4224,16384] = W[4224,512] * X^T via mma.sync m16n8k16,
// fp16 2-term split (AhBh + AlBh; B uses hi only), fp32 accumulate.
// Error model: dropped |A||B_lo| term ~2^-12 norm-relative ≈ 2.4e-4 < 1e-3.
// 128-thr CTAs (occ 2), tile 128x128, 4-stage cp.async pipeline.
// ============================================================================

#define DDIM 512
#define M_ROWS 4224
#define NKT 16               // 512 / 32
#define KT 32

#define STAGE_BYTES 24576    // Ah 8K + Al 8K + Bh 8K
#define A_H_OFF 0
#define A_L_OFF 8192
#define B_H_OFF 16384
#define NSTAGE 4
#define SMEM_TOTAL (NSTAGE * STAGE_BYTES)   // 98304 per CTA, occ 2 -> 192K/SM

__device__ __half g_w_hi[M_ROWS * DDIM];
__device__ __half g_w_lo[M_ROWS * DDIM];
__device__ __half g_e_hi[16 * 1024 * DDIM];

// ---------------------------------------------------------------------------
__device__ __forceinline__ uint32_t smem_u32(const void* p) {
    uint32_t a;
    asm("{ .reg .u64 t; cvta.to.shared.u64 t, %1; cvt.u32.u64 %0, t; }"
        : "=r"(a) : "l"(p));
    return a;
}
__device__ __forceinline__ void cpa16(uint32_t dst, const void* src) {
    asm volatile("cp.async.cg.shared.global [%0], [%1], 16;"
                 :: "r"(dst), "l"(src));
}
__device__ __forceinline__ void cp_commit() {
    asm volatile("cp.async.commit_group;" ::: "memory");
}
__device__ __forceinline__ void cp_wait0() {
    asm volatile("cp.async.wait_group 0;" ::: "memory");
}
__device__ __forceinline__ void cp_wait1() {
    asm volatile("cp.async.wait_group 1;" ::: "memory");
}
__device__ __forceinline__ void cp_wait2() {
    asm volatile("cp.async.wait_group 2;" ::: "memory");
}
__device__ __forceinline__ void ldsm4(uint32_t* r, uint32_t addr) {
    asm volatile("ldmatrix.sync.aligned.m8n8.x4.shared.b16 {%0,%1,%2,%3}, [%4];"
                 : "=r"(r[0]), "=r"(r[1]), "=r"(r[2]), "=r"(r[3]) : "r"(addr));
}
__device__ __forceinline__ void mma16816(float* d, const uint32_t* a,
                                         const uint32_t* b) {
    asm volatile(
        "mma.sync.aligned.m16n8k16.row.col.f32.f16.f16.f32 "
        "{%0,%1,%2,%3}, {%4,%5,%6,%7}, {%8,%9}, {%0,%1,%2,%3};"
        : "+f"(d[0]), "+f"(d[1]), "+f"(d[2]), "+f"(d[3])
        : "r"(a[0]), "r"(a[1]), "r"(a[2]), "r"(a[3]), "r"(b[0]), "r"(b[1]));
}
__device__ __forceinline__ uint32_t swoff(int row, int g) {
    return (uint32_t)(row * 64 + ((g ^ ((row >> 1) & 3)) << 4));
}

// ---------------------------------------------------------------------------
__global__ void convert_emb_kernel(const float* __restrict__ emb) {
    int i = blockIdx.x * blockDim.x + threadIdx.x;   // 2097152 float4
    float4 v = ((const float4*)emb)[i];
    __half h0 = __float2half(v.x), h1 = __float2half(v.y);
    __half h2 = __float2half(v.z), h3 = __float2half(v.w);
    __half2* ph = (__half2*)&g_e_hi[(size_t)i * 4];
    ph[0] = __halves2half2(h0, h1);
    ph[1] = __halves2half2(h2, h3);
}

__global__ void convert_w_kernel(const float* __restrict__ topic_w,
                                 const float* __restrict__ shared_w) {
    int i = blockIdx.x * blockDim.x + threadIdx.x;   // 540672 float4
    const int topic_vec = (4096 * 512) / 4;
    float4 v = (i < topic_vec) ? ((const float4*)topic_w)[i]
                               : ((const float4*)shared_w)[i - topic_vec];
    __half h0 = __float2half(v.x), h1 = __float2half(v.y);
    __half h2 = __float2half(v.z), h3 = __float2half(v.w);
    __half l0 = __float2half(v.x - __half2float(h0));
    __half l1 = __float2half(v.y - __half2float(h1));
    __half l2 = __float2half(v.z - __half2float(h2));
    __half l3 = __float2half(v.w - __half2float(h3));
    __half2* ph = (__half2*)&g_w_hi[(size_t)i * 4];
    ph[0] = __halves2half2(h0, h1);
    ph[1] = __halves2half2(h2, h3);
    __half2* pl = (__half2*)&g_w_lo[(size_t)i * 4];
    pl[0] = __halves2half2(l0, l1);
    pl[1] = __halves2half2(l2, l3);
}

// ---------------------------------------------------------------------------
// stage loader: A hi+lo (128x32) + B hi (128x32); 128 threads, 12 chunks each
// ---------------------------------------------------------------------------
__device__ __forceinline__ void issue_stage(
    uint32_t sbuf, int tid, int kt,
    const __half* __restrict__ Wh, const __half* __restrict__ Wl,
    const __half* __restrict__ Eh)
{
    const int koff = kt * KT;
#pragma unroll
    for (int i = 0; i < 4; i++) {          // 512 chunks per matrix
        int c = tid + i * 128;
        int row = c >> 2, g = c & 3;
        uint32_t d = swoff(row, g);
        const size_t goff = (size_t)row * DDIM + koff + g * 8;
        cpa16(sbuf + A_H_OFF + d, Wh + goff);
        cpa16(sbuf + A_L_OFF + d, Wl + goff);
        cpa16(sbuf + B_H_OFF + d, Eh + goff);
    }
}

// ---------------------------------------------------------------------------
// Main GEMM: grid (128, 36). x: bIdx*8 + l-tile (N=128). y<32: topic tile
// (M=128). y in 32..35: shared rows, each replica writes 8 topic copies.
// 4 warps (2Mx2N), each 64x64.
// ---------------------------------------------------------------------------
__global__ __launch_bounds__(128, 2)
void topic_mma_kernel(const float* __restrict__ topic_b,
                      const float* __restrict__ shared_b,
                      float* __restrict__ out)
{
    extern __shared__ char smem[];
    const uint32_t sb = smem_u32(smem);
    const int tid = threadIdx.x;
    const int wid = tid >> 5, lane = tid & 31;
    const int wm = wid & 1, wn = wid >> 1;   // 2(M) x 2(N)

    const int tileN = blockIdx.x;            // 0..127
    const int tileM = blockIdx.y;            // 0..35
    const bool is_sh = (tileM >= 32);
    const int m0 = is_sh ? 4096 : tileM * 128;
    const int bIdx = tileN >> 3;
    const int l0 = (tileN & 7) * 128;

    const __half* Wh = g_w_hi + (size_t)m0 * DDIM;
    const __half* Wl = g_w_lo + (size_t)m0 * DDIM;
    const __half* Eh = g_e_hi + (size_t)(bIdx * 1024 + l0) * DDIM;

    // ldmatrix lane-address components (non-trans, K-major both operands)
    const int a_row = wm * 64 + (lane & 15);
    const int a_gl = lane >> 4;
    const uint32_t a_sw = ((lane & 15) >> 1) & 3;
    const int b_row = wn * 64 + (lane & 7) + ((lane >> 4) << 3);
    const int b_gl = (lane >> 3) & 1;
    const uint32_t b_sw = ((lane & 7) >> 1) & 3;

    float acc[4][8][4];
#pragma unroll
    for (int mf = 0; mf < 4; mf++)
#pragma unroll
        for (int nf = 0; nf < 8; nf++)
#pragma unroll
            for (int r = 0; r < 4; r++) acc[mf][nf][r] = 0.f;

    // 4-stage prologue: stages 0..2 in flight
    issue_stage(sb + 0 * STAGE_BYTES, tid, 0, Wh, Wl, Eh);
    cp_commit();
    issue_stage(sb + 1 * STAGE_BYTES, tid, 1, Wh, Wl, Eh);
    cp_commit();
    issue_stage(sb + 2 * STAGE_BYTES, tid, 2, Wh, Wl, Eh);
    cp_commit();

    for (int kt = 0; kt < NKT; ++kt) {
        if (kt < NKT - 2) cp_wait2();
        else if (kt == NKT - 2) cp_wait1();
        else cp_wait0();
        __syncthreads();

        if (kt + 3 < NKT) {
            issue_stage(sb + ((kt + 3) % NSTAGE) * STAGE_BYTES, tid, kt + 3,
                        Wh, Wl, Eh);
            cp_commit();
        }

        const uint32_t st = sb + (kt % NSTAGE) * STAGE_BYTES;
#pragma unroll
        for (int kk = 0; kk < 2; kk++) {
            uint32_t ah[4][4], al[4][4], bh[4][4];
#pragma unroll
            for (int mf = 0; mf < 4; mf++) {
                uint32_t off = (uint32_t)((a_row + mf * 16) * 64) +
                               (((kk * 2 + a_gl) ^ a_sw) << 4);
                ldsm4(ah[mf], st + A_H_OFF + off);
                ldsm4(al[mf], st + A_L_OFF + off);
            }
#pragma unroll
            for (int np = 0; np < 4; np++) {
                uint32_t off = (uint32_t)((b_row + np * 16) * 64) +
                               (((kk * 2 + b_gl) ^ b_sw) << 4);
                ldsm4(bh[np], st + B_H_OFF + off);
            }
#pragma unroll
            for (int mf = 0; mf < 4; mf++)
#pragma unroll
                for (int np = 0; np < 4; np++) {
                    mma16816(acc[mf][np * 2],     ah[mf], &bh[np][0]);
                    mma16816(acc[mf][np * 2 + 1], ah[mf], &bh[np][2]);
                    mma16816(acc[mf][np * 2],     al[mf], &bh[np][0]);
                    mma16816(acc[mf][np * 2 + 1], al[mf], &bh[np][2]);
                }
        }
    }

    // ---- epilogue: bias + float2 stores ----------------------------------
    const float* bp = is_sh ? shared_b : (topic_b + tileM * 128);
    const int gid = lane >> 2, tig = lane & 3;
    const int cbase = l0 + wn * 64 + tig * 2;

#pragma unroll
    for (int mf = 0; mf < 4; mf++) {
        const int r0 = wm * 64 + mf * 16 + gid;
        const int r1 = r0 + 8;
        const float bias0 = bp[r0];
        const float bias1 = bp[r1];
        if (!is_sh) {
            const size_t base = ((size_t)(tileM * 16 + bIdx) * 256) * 1024;
            float* p0 = out + base + (size_t)r0 * 1024 + cbase;
            float* p1 = out + base + (size_t)r1 * 1024 + cbase;
#pragma unroll
            for (int nf = 0; nf < 8; nf++) {
                float2 v0 = make_float2(acc[mf][nf][0] + bias0,
                                        acc[mf][nf][1] + bias0);
                float2 v1 = make_float2(acc[mf][nf][2] + bias1,
                                        acc[mf][nf][3] + bias1);
                *(float2*)(p0 + nf * 8) = v0;
                *(float2*)(p1 + nf * 8) = v1;
            }
        } else {
#pragma unroll 1
            for (int tt = 0; tt < 8; tt++) {
                const int t = (tileM - 32) * 8 + tt;
                const size_t base =
                    ((size_t)(t * 16 + bIdx) * 256 + 128) * 1024;
                float* p0 = out + base + (size_t)r0 * 1024 + cbase;
                float* p1 = out + base + (size_t)r1 * 1024 + cbase;
#pragma unroll
                for (int nf = 0; nf < 8; nf++) {
                    float2 v0 = make_float2(acc[mf][nf][0] + bias0,
                                            acc[mf][nf][1] + bias0);
                    float2 v1 = make_float2(acc[mf][nf][2] + bias1,
                                            acc[mf][nf][3] + bias1);
                    *(float2*)(p0 + nf * 8) = v0;
                    *(float2*)(p1 + nf * 8) = v1;
                }
            }
        }
    }
}

// ---------------------------------------------------------------------------
extern "C" void kernel_launch(void* const* d_in, const int* in_sizes, int n_in,
                              void* d_out, int out_size) {
    const float* emb      = (const float*)d_in[0];  // [16,1024,512]
    const float* topic_w  = (const float*)d_in[1];  // [32,128,512]
    const float* topic_b  = (const float*)d_in[2];  // [32,128]
    const float* shared_w = (const float*)d_in[3];  // [128,512]
    const float* shared_b = (const float*)d_in[4];  // [128]
    float* out = (float*)d_out;                     // [32,16,256,1024]

    convert_emb_kernel<<<8192, 256>>>(emb);
    convert_w_kernel<<<2112, 256>>>(topic_w, shared_w);

    cudaFuncSetAttribute(topic_mma_kernel,
                         cudaFuncAttributeMaxDynamicSharedMemorySize,
                         SMEM_TOTAL);
    dim3 grid(128, 36);
    topic_mma_kernel<<<grid, 128, SMEM_TOTAL>>>(topic_b, shared_b, out);
}

// round 9
// speedup vs baseline: 6.4529x; 1.5932x over previous
#include <cuda_runtime.h>
#include <cuda_fp16.h>
#include <cstdint>

// ============================================================================
// TopicLayer GEMM C[4224,16384] = W[4224,512] * X^T via mma.sync m16n8k16,
// pure fp16 operands (1-term), fp32 accumulate.
// Error model (calibrated R8): B-rounding alone measured 2.07e-4; adding
// A-rounding (same stats) -> ~2.9e-4 expected, gate is 1e-3.
// 128-thr CTAs (occ 2), tile 128x128, 4-stage cp.async pipeline.
// ============================================================================

#define DDIM 512
#define M_ROWS 4224
#define NKT 16               // 512 / 32
#define KT 32

#define STAGE_BYTES 16384    // Ah 8K + Bh 8K
#define A_H_OFF 0
#define B_H_OFF 8192
#define NSTAGE 4
#define SMEM_TOTAL (NSTAGE * STAGE_BYTES)   // 65536 per CTA, occ 2 -> 128K/SM

__device__ __half g_w_hi[M_ROWS * DDIM];
__device__ __half g_e_hi[16 * 1024 * DDIM];

// ---------------------------------------------------------------------------
__device__ __forceinline__ uint32_t smem_u32(const void* p) {
    uint32_t a;
    asm("{ .reg .u64 t; cvta.to.shared.u64 t, %1; cvt.u32.u64 %0, t; }"
        : "=r"(a) : "l"(p));
    return a;
}
__device__ __forceinline__ void cpa16(uint32_t dst, const void* src) {
    asm volatile("cp.async.cg.shared.global [%0], [%1], 16;"
                 :: "r"(dst), "l"(src));
}
__device__ __forceinline__ void cp_commit() {
    asm volatile("cp.async.commit_group;" ::: "memory");
}
__device__ __forceinline__ void cp_wait0() {
    asm volatile("cp.async.wait_group 0;" ::: "memory");
}
__device__ __forceinline__ void cp_wait1() {
    asm volatile("cp.async.wait_group 1;" ::: "memory");
}
__device__ __forceinline__ void cp_wait2() {
    asm volatile("cp.async.wait_group 2;" ::: "memory");
}
__device__ __forceinline__ void ldsm4(uint32_t* r, uint32_t addr) {
    asm volatile("ldmatrix.sync.aligned.m8n8.x4.shared.b16 {%0,%1,%2,%3}, [%4];"
                 : "=r"(r[0]), "=r"(r[1]), "=r"(r[2]), "=r"(r[3]) : "r"(addr));
}
__device__ __forceinline__ void mma16816(float* d, const uint32_t* a,
                                         const uint32_t* b) {
    asm volatile(
        "mma.sync.aligned.m16n8k16.row.col.f32.f16.f16.f32 "
        "{%0,%1,%2,%3}, {%4,%5,%6,%7}, {%8,%9}, {%0,%1,%2,%3};"
        : "+f"(d[0]), "+f"(d[1]), "+f"(d[2]), "+f"(d[3])
        : "r"(a[0]), "r"(a[1]), "r"(a[2]), "r"(a[3]), "r"(b[0]), "r"(b[1]));
}
__device__ __forceinline__ uint32_t swoff(int row, int g) {
    return (uint32_t)(row * 64 + ((g ^ ((row >> 1) & 3)) << 4));
}

// ---------------------------------------------------------------------------
__global__ void convert_emb_kernel(const float* __restrict__ emb) {
    int i = blockIdx.x * blockDim.x + threadIdx.x;   // 2097152 float4
    float4 v = ((const float4*)emb)[i];
    __half2* ph = (__half2*)&g_e_hi[(size_t)i * 4];
    ph[0] = __halves2half2(__float2half(v.x), __float2half(v.y));
    ph[1] = __halves2half2(__float2half(v.z), __float2half(v.w));
}

__global__ void convert_w_kernel(const float* __restrict__ topic_w,
                                 const float* __restrict__ shared_w) {
    int i = blockIdx.x * blockDim.x + threadIdx.x;   // 540672 float4
    const int topic_vec = (4096 * 512) / 4;
    float4 v = (i < topic_vec) ? ((const float4*)topic_w)[i]
                               : ((const float4*)shared_w)[i - topic_vec];
    __half2* ph = (__half2*)&g_w_hi[(size_t)i * 4];
    ph[0] = __halves2half2(__float2half(v.x), __float2half(v.y));
    ph[1] = __halves2half2(__float2half(v.z), __float2half(v.w));
}

// ---------------------------------------------------------------------------
// stage loader: A hi (128x32) + B hi (128x32); 128 threads, 8 chunks each
// ---------------------------------------------------------------------------
__device__ __forceinline__ void issue_stage(
    uint32_t sbuf, int tid, int kt,
    const __half* __restrict__ Wh, const __half* __restrict__ Eh)
{
    const int koff = kt * KT;
#pragma unroll
    for (int i = 0; i < 4; i++) {          // 512 chunks per matrix
        int c = tid + i * 128;
        int row = c >> 2, g = c & 3;
        uint32_t d = swoff(row, g);
        const size_t goff = (size_t)row * DDIM + koff + g * 8;
        cpa16(sbuf + A_H_OFF + d, Wh + goff);
        cpa16(sbuf + B_H_OFF + d, Eh + goff);
    }
}

// ---------------------------------------------------------------------------
// Main GEMM: grid (128, 36). x: bIdx*8 + l-tile (N=128). y<32: topic tile
// (M=128). y in 32..35: shared rows, each replica writes 8 topic copies.
// 4 warps (2Mx2N), each 64x64.
// ---------------------------------------------------------------------------
__global__ __launch_bounds__(128, 2)
void topic_mma_kernel(const float* __restrict__ topic_b,
                      const float* __restrict__ shared_b,
                      float* __restrict__ out)
{
    extern __shared__ char smem[];
    const uint32_t sb = smem_u32(smem);
    const int tid = threadIdx.x;
    const int wid = tid >> 5, lane = tid & 31;
    const int wm = wid & 1, wn = wid >> 1;   // 2(M) x 2(N)

    const int tileN = blockIdx.x;            // 0..127
    const int tileM = blockIdx.y;            // 0..35
    const bool is_sh = (tileM >= 32);
    const int m0 = is_sh ? 4096 : tileM * 128;
    const int bIdx = tileN >> 3;
    const int l0 = (tileN & 7) * 128;

    const __half* Wh = g_w_hi + (size_t)m0 * DDIM;
    const __half* Eh = g_e_hi + (size_t)(bIdx * 1024 + l0) * DDIM;

    // ldmatrix lane-address components (non-trans, K-major both operands)
    const int a_row = wm * 64 + (lane & 15);
    const int a_gl = lane >> 4;
    const uint32_t a_sw = ((lane & 15) >> 1) & 3;
    const int b_row = wn * 64 + (lane & 7) + ((lane >> 4) << 3);
    const int b_gl = (lane >> 3) & 1;
    const uint32_t b_sw = ((lane & 7) >> 1) & 3;

    float acc[4][8][4];
#pragma unroll
    for (int mf = 0; mf < 4; mf++)
#pragma unroll
        for (int nf = 0; nf < 8; nf++)
#pragma unroll
            for (int r = 0; r < 4; r++) acc[mf][nf][r] = 0.f;

    // 4-stage prologue: stages 0..2 in flight
    issue_stage(sb + 0 * STAGE_BYTES, tid, 0, Wh, Eh);
    cp_commit();
    issue_stage(sb + 1 * STAGE_BYTES, tid, 1, Wh, Eh);
    cp_commit();
    issue_stage(sb + 2 * STAGE_BYTES, tid, 2, Wh, Eh);
    cp_commit();

    for (int kt = 0; kt < NKT; ++kt) {
        if (kt < NKT - 2) cp_wait2();
        else if (kt == NKT - 2) cp_wait1();
        else cp_wait0();
        __syncthreads();

        if (kt + 3 < NKT) {
            issue_stage(sb + ((kt + 3) % NSTAGE) * STAGE_BYTES, tid, kt + 3,
                        Wh, Eh);
            cp_commit();
        }

        const uint32_t st = sb + (kt % NSTAGE) * STAGE_BYTES;
#pragma unroll
        for (int kk = 0; kk < 2; kk++) {
            uint32_t ah[4][4], bh[4][4];
#pragma unroll
            for (int mf = 0; mf < 4; mf++) {
                uint32_t off = (uint32_t)((a_row + mf * 16) * 64) +
                               (((kk * 2 + a_gl) ^ a_sw) << 4);
                ldsm4(ah[mf], st + A_H_OFF + off);
            }
#pragma unroll
            for (int np = 0; np < 4; np++) {
                uint32_t off = (uint32_t)((b_row + np * 16) * 64) +
                               (((kk * 2 + b_gl) ^ b_sw) << 4);
                ldsm4(bh[np], st + B_H_OFF + off);
            }
#pragma unroll
            for (int mf = 0; mf < 4; mf++)
#pragma unroll
                for (int np = 0; np < 4; np++) {
                    mma16816(acc[mf][np * 2],     ah[mf], &bh[np][0]);
                    mma16816(acc[mf][np * 2 + 1], ah[mf], &bh[np][2]);
                }
        }
    }

    // ---- epilogue: bias + float2 stores ----------------------------------
    const float* bp = is_sh ? shared_b : (topic_b + tileM * 128);
    const int gid = lane >> 2, tig = lane & 3;
    const int cbase = l0 + wn * 64 + tig * 2;

#pragma unroll
    for (int mf = 0; mf < 4; mf++) {
        const int r0 = wm * 64 + mf * 16 + gid;
        const int r1 = r0 + 8;
        const float bias0 = bp[r0];
        const float bias1 = bp[r1];
        if (!is_sh) {
            const size_t base = ((size_t)(tileM * 16 + bIdx) * 256) * 1024;
            float* p0 = out + base + (size_t)r0 * 1024 + cbase;
            float* p1 = out + base + (size_t)r1 * 1024 + cbase;
#pragma unroll
            for (int nf = 0; nf < 8; nf++) {
                float2 v0 = make_float2(acc[mf][nf][0] + bias0,
                                        acc[mf][nf][1] + bias0);
                float2 v1 = make_float2(acc[mf][nf][2] + bias1,
                                        acc[mf][nf][3] + bias1);
                *(float2*)(p0 + nf * 8) = v0;
                *(float2*)(p1 + nf * 8) = v1;
            }
        } else {
#pragma unroll 1
            for (int tt = 0; tt < 8; tt++) {
                const int t = (tileM - 32) * 8 + tt;
                const size_t base =
                    ((size_t)(t * 16 + bIdx) * 256 + 128) * 1024;
                float* p0 = out + base + (size_t)r0 * 1024 + cbase;
                float* p1 = out + base + (size_t)r1 * 1024 + cbase;
#pragma unroll
                for (int nf = 0; nf < 8; nf++) {
                    float2 v0 = make_float2(acc[mf][nf][0] + bias0,
                                            acc[mf][nf][1] + bias0);
                    float2 v1 = make_float2(acc[mf][nf][2] + bias1,
                                            acc[mf][nf][3] + bias1);
                    *(float2*)(p0 + nf * 8) = v0;
                    *(float2*)(p1 + nf * 8) = v1;
                }
            }
        }
    }
}

// ---------------------------------------------------------------------------
extern "C" void kernel_launch(void* const* d_in, const int* in_sizes, int n_in,
                              void* d_out, int out_size) {
    const float* emb      = (const float*)d_in[0];  // [16,1024,512]
    const float* topic_w  = (const float*)d_in[1];  // [32,128,512]
    const float* topic_b  = (const float*)d_in[2];  // [32,128]
    const float* shared_w = (const float*)d_in[3];  // [128,512]
    const float* shared_b = (const float*)d_in[4];  // [128]
    float* out = (float*)d_out;                     // [32,16,256,1024]

    convert_emb_kernel<<<8192, 256>>>(emb);
    convert_w_kernel<<<2112, 256>>>(topic_w, shared_w);

    cudaFuncSetAttribute(topic_mma_kernel,
                         cudaFuncAttributeMaxDynamicSharedMemorySize,
                         SMEM_TOTAL);
    dim3 grid(128, 36);
    topic_mma_kernel<<<grid, 128, SMEM_TOTAL>>>(topic_b, shared_b, out);
}